// round 7
// baseline (speedup 1.0000x reference)
#include <cuda_runtime.h>
#include <math.h>
#include <stdint.h>

// Problem constants
#define BB 4
#define LL 2048
#define SS 2048
#define DD 1024
#define HH 16
#define HD 64
#define MM (BB * LL)   // 8192 rows for all projection GEMMs

// Scratch (device globals: allocation-free rule)
__device__ float g_Qh[BB * HH * LL * HD];   // [B,H,L,hd] 32MB
__device__ float g_Kh[BB * HH * SS * HD];   // [B,H,S,hd] 32MB
__device__ float g_Vh[BB * HH * SS * HD];   // [B,H,S,hd] 32MB
__device__ float g_AO[BB * LL * DD];        // [B,L,D]    32MB (tf32-rounded)
// TF32-rounded operand copies (so the GEMM inner loop needs no cvt)
__device__ float g_qR[MM * DD];             // 32MB
__device__ float g_kR[MM * DD];             // 32MB
__device__ float g_vR[MM * DD];             // 32MB
__device__ float g_WqR[DD * DD];            // 4MB
__device__ float g_WkR[DD * DD];            // 4MB
__device__ float g_WvR[DD * DD];            // 4MB
__device__ float g_WoR[DD * DD];            // 4MB

__device__ __forceinline__ uint32_t f2tf32(float f) {
    uint32_t r;
    asm("cvt.rna.tf32.f32 %0, %1;" : "=r"(r) : "f"(f));
    return r;
}

// ---------------------------------------------------------------------------
// Prepass: round fp32 -> tf32-in-fp32 (low 13 mantissa bits zeroed).
// Bandwidth-bound; grid-stride float4.
// ---------------------------------------------------------------------------
__global__ __launch_bounds__(256) void round_tf32_kernel(
    const float* __restrict__ in, float* __restrict__ out, int n4)
{
    int i = blockIdx.x * blockDim.x + threadIdx.x;
    int stride = gridDim.x * blockDim.x;
    for (; i < n4; i += stride) {
        float4 v = ((const float4*)in)[i];
        uint4 r;
        r.x = f2tf32(v.x); r.y = f2tf32(v.y);
        r.z = f2tf32(v.z); r.w = f2tf32(v.w);
        ((uint4*)out)[i] = r;
    }
}

// ---------------------------------------------------------------------------
// TF32 tensor-core GEMM: Y[m,n] = sum_k X[m,k] * W[n,k]  (x @ W.T)
// Operands are PRE-ROUNDED to tf32 -> inner loop loads raw bits (no cvt).
// M=8192, N=1024, K=1024. 128x128x16 tile, 8 warps (2x4), warp tile 64x32,
// mma.sync.m16n8k8.tf32, cp.async double-buffered smem.
// SPLIT_HEADS=1: write Y as [B,H,seq,HD] (fused head-split transpose).
// ---------------------------------------------------------------------------
#define GBK 16
#define GSTRIDE 20          // padded row stride in floats (conflict-free)
#define GBUF (128 * GSTRIDE)

__device__ __forceinline__ void mma_tf32(float* d, const uint32_t* a, const uint32_t* b) {
    asm volatile(
        "mma.sync.aligned.m16n8k8.row.col.f32.tf32.tf32.f32 "
        "{%0,%1,%2,%3},{%4,%5,%6,%7},{%8,%9},{%0,%1,%2,%3};"
        : "+f"(d[0]), "+f"(d[1]), "+f"(d[2]), "+f"(d[3])
        : "r"(a[0]), "r"(a[1]), "r"(a[2]), "r"(a[3]), "r"(b[0]), "r"(b[1]));
}

__device__ __forceinline__ void cp16(uint32_t smem_addr, const void* gptr) {
    asm volatile("cp.async.cg.shared.global [%0], [%1], 16;\n"
                 :: "r"(smem_addr), "l"(gptr));
}

template <int SPLIT_HEADS>
__global__ __launch_bounds__(256) void gemm_tf32_kernel(
    const float* __restrict__ X, const float* __restrict__ W,
    float* __restrict__ Y)
{
    __shared__ float As[2][GBUF];
    __shared__ float Bs[2][GBUF];

    const int tid = threadIdx.x;
    const int bm = blockIdx.y * 128;
    const int bn = blockIdx.x * 128;
    const int lane = tid & 31;
    const int warp = tid >> 5;
    const int wm = (warp >> 2) * 64;   // warp M offset within block tile
    const int wn = (warp & 3) * 32;    // warp N offset
    const int gid = lane >> 2;         // 0..7
    const int tig = lane & 3;          // 0..3

    // cp.async chunk mapping: 512 16B-chunks per operand per tile; 2/thread
    const int r0c = (tid) >> 2, k0c = (tid & 3) * 4;
    const int r1c = (tid + 256) >> 2, k1c = ((tid + 256) & 3) * 4;

    uint32_t sA[2][2], sB[2][2];
    {
        uint32_t aBase0 = (uint32_t)__cvta_generic_to_shared(&As[0][0]);
        uint32_t aBase1 = (uint32_t)__cvta_generic_to_shared(&As[1][0]);
        uint32_t bBase0 = (uint32_t)__cvta_generic_to_shared(&Bs[0][0]);
        uint32_t bBase1 = (uint32_t)__cvta_generic_to_shared(&Bs[1][0]);
        sA[0][0] = aBase0 + (r0c * GSTRIDE + k0c) * 4;
        sA[0][1] = aBase0 + (r1c * GSTRIDE + k1c) * 4;
        sA[1][0] = aBase1 + (r0c * GSTRIDE + k0c) * 4;
        sA[1][1] = aBase1 + (r1c * GSTRIDE + k1c) * 4;
        sB[0][0] = bBase0 + (r0c * GSTRIDE + k0c) * 4;
        sB[0][1] = bBase0 + (r1c * GSTRIDE + k1c) * 4;
        sB[1][0] = bBase1 + (r0c * GSTRIDE + k0c) * 4;
        sB[1][1] = bBase1 + (r1c * GSTRIDE + k1c) * 4;
    }

    float acc[4][4][4];
#pragma unroll
    for (int mi = 0; mi < 4; mi++)
#pragma unroll
        for (int ni = 0; ni < 4; ni++)
#pragma unroll
            for (int r = 0; r < 4; r++) acc[mi][ni][r] = 0.f;

    // prologue: tile 0 -> buf 0
    {
        cp16(sA[0][0], X + (size_t)(bm + r0c) * DD + k0c);
        cp16(sA[0][1], X + (size_t)(bm + r1c) * DD + k1c);
        cp16(sB[0][0], W + (size_t)(bn + r0c) * DD + k0c);
        cp16(sB[0][1], W + (size_t)(bn + r1c) * DD + k1c);
        asm volatile("cp.async.commit_group;\n" ::: "memory");
    }

    const int NT = DD / GBK;  // 64
    for (int t = 0; t < NT; t++) {
        asm volatile("cp.async.wait_group 0;\n" ::: "memory");
        __syncthreads();

        if (t + 1 < NT) {
            const int kt = (t + 1) * GBK;
            const int nb = (t + 1) & 1;
            cp16(sA[nb][0], X + (size_t)(bm + r0c) * DD + kt + k0c);
            cp16(sA[nb][1], X + (size_t)(bm + r1c) * DD + kt + k1c);
            cp16(sB[nb][0], W + (size_t)(bn + r0c) * DD + kt + k0c);
            cp16(sB[nb][1], W + (size_t)(bn + r1c) * DD + kt + k1c);
            asm volatile("cp.async.commit_group;\n" ::: "memory");
        }

        const uint32_t* Ab = (const uint32_t*)As[t & 1];
        const uint32_t* Bb = (const uint32_t*)Bs[t & 1];
#pragma unroll
        for (int step = 0; step < 2; step++) {
            const int k0 = step * 8 + tig;
            uint32_t a[4][4], b[4][2];
#pragma unroll
            for (int mi = 0; mi < 4; mi++) {
                const uint32_t* pa = Ab + (wm + mi * 16 + gid) * GSTRIDE + k0;
                a[mi][0] = pa[0];
                a[mi][1] = pa[8 * GSTRIDE];
                a[mi][2] = pa[4];
                a[mi][3] = pa[8 * GSTRIDE + 4];
            }
#pragma unroll
            for (int ni = 0; ni < 4; ni++) {
                const uint32_t* pb = Bb + (wn + ni * 8 + gid) * GSTRIDE + k0;
                b[ni][0] = pb[0];
                b[ni][1] = pb[4];
            }
#pragma unroll
            for (int mi = 0; mi < 4; mi++)
#pragma unroll
                for (int ni = 0; ni < 4; ni++)
                    mma_tf32(acc[mi][ni], a[mi], b[ni]);
        }
        __syncthreads();
    }

    // epilogue
#pragma unroll
    for (int mi = 0; mi < 4; mi++) {
#pragma unroll
        for (int ni = 0; ni < 4; ni++) {
            int r0 = bm + wm + mi * 16 + gid;
            int r1 = r0 + 8;
            int c0 = bn + wn + ni * 8 + tig * 2;
            float2 lo = make_float2(acc[mi][ni][0], acc[mi][ni][1]);
            float2 hi = make_float2(acc[mi][ni][2], acc[mi][ni][3]);
            if (SPLIT_HEADS) {
                int b0 = r0 >> 11, l0 = r0 & 2047;
                int b1 = r1 >> 11, l1 = r1 & 2047;
                int h = c0 >> 6, hd = c0 & 63;
                *(float2*)(Y + (((size_t)(b0 * HH + h) * LL + l0) * HD + hd)) = lo;
                *(float2*)(Y + (((size_t)(b1 * HH + h) * LL + l1) * HD + hd)) = hi;
            } else {
                *(float2*)(Y + (size_t)r0 * DD + c0) = lo;
                *(float2*)(Y + (size_t)r1 * DD + c0) = hi;
            }
        }
    }
}

// ---------------------------------------------------------------------------
// Flash attention (causal). 1 thread = 1 query row. Output rounded to tf32
// (feeds the final GEMM, which expects pre-rounded operands).
// ---------------------------------------------------------------------------
__global__ __launch_bounds__(128) void flash_attn_kernel(
    const float* __restrict__ Qh, const float* __restrict__ Kh,
    const float* __restrict__ Vh, float* __restrict__ AO)
{
    __shared__ float Ks[64][HD + 4];
    __shared__ float Vs[64][HD + 4];

    const int bh = blockIdx.y;          // b*H + h
    const int b = bh >> 4;
    const int h = bh & 15;
    const int l = blockIdx.x * 128 + threadIdx.x;

    const float* Qb = Qh + (size_t)bh * (LL * HD);
    const float* Kb = Kh + (size_t)bh * (SS * HD);
    const float* Vb = Vh + (size_t)bh * (SS * HD);

    float q[64], o[64];
#pragma unroll
    for (int i = 0; i < 16; i++) {
        float4 t = *(const float4*)(Qb + (size_t)l * HD + i * 4);
        q[4 * i + 0] = t.x; q[4 * i + 1] = t.y;
        q[4 * i + 2] = t.z; q[4 * i + 3] = t.w;
    }
#pragma unroll
    for (int d = 0; d < 64; d++) o[d] = 0.f;

    float mx = -1e30f, lsum = 0.f;
    const int ntiles = blockIdx.x * 2 + 2;

    for (int jt = 0; jt < ntiles; jt++) {
        const int s0 = jt * 64;
        __syncthreads();
#pragma unroll
        for (int i = 0; i < 8; i++) {
            int t = threadIdx.x + i * 128;
            int r = t >> 4;
            int c = (t & 15) * 4;
            *(float4*)(&Ks[r][c]) = *(const float4*)(Kb + (size_t)(s0 + r) * HD + c);
            *(float4*)(&Vs[r][c]) = *(const float4*)(Vb + (size_t)(s0 + r) * HD + c);
        }
        __syncthreads();

#pragma unroll 1
        for (int c0 = 0; c0 < 64; c0 += 8) {
            float sc[8];
            float cm = -1e30f;
#pragma unroll
            for (int s = 0; s < 8; s++) {
                float a0 = 0.f, a1 = 0.f, a2 = 0.f, a3 = 0.f;
#pragma unroll
                for (int d4 = 0; d4 < 16; d4++) {
                    float4 kk = *(const float4*)(&Ks[c0 + s][d4 * 4]);
                    a0 += q[d4 * 4 + 0] * kk.x;
                    a1 += q[d4 * 4 + 1] * kk.y;
                    a2 += q[d4 * 4 + 2] * kk.z;
                    a3 += q[d4 * 4 + 3] * kk.w;
                }
                float v = ((a0 + a1) + (a2 + a3)) * 0.125f;
                if (s0 + c0 + s > l) v = -1e30f;
                sc[s] = v;
                cm = fmaxf(cm, v);
            }
            float mnew = fmaxf(mx, cm);
            if (mnew != mx) {
                float corr = __expf(mx - mnew);
                lsum *= corr;
#pragma unroll
                for (int d = 0; d < 64; d++) o[d] *= corr;
                mx = mnew;
            }
#pragma unroll
            for (int s = 0; s < 8; s++) {
                float p = __expf(sc[s] - mx);
                lsum += p;
#pragma unroll
                for (int d4 = 0; d4 < 16; d4++) {
                    float4 vv = *(const float4*)(&Vs[c0 + s][d4 * 4]);
                    o[d4 * 4 + 0] += p * vv.x;
                    o[d4 * 4 + 1] += p * vv.y;
                    o[d4 * 4 + 2] += p * vv.z;
                    o[d4 * 4 + 3] += p * vv.w;
                }
            }
        }
    }

    const float inv = 1.f / lsum;
    float* dst = AO + ((size_t)(b * LL) + l) * DD + h * HD;
#pragma unroll
    for (int i = 0; i < 16; i++) {
        uint4 t;
        t.x = f2tf32(o[4 * i + 0] * inv);
        t.y = f2tf32(o[4 * i + 1] * inv);
        t.z = f2tf32(o[4 * i + 2] * inv);
        t.w = f2tf32(o[4 * i + 3] * inv);
        *(uint4*)(dst + 4 * i) = t;
    }
}

// ---------------------------------------------------------------------------
// Launch
// ---------------------------------------------------------------------------
extern "C" void kernel_launch(void* const* d_in, const int* in_sizes, int n_in,
                              void* d_out, int out_size)
{
    const float* q  = (const float*)d_in[0];
    const float* k  = (const float*)d_in[1];
    const float* v  = (const float*)d_in[2];
    // d_in[3] = mask (causal, known analytically — unused)
    const float* Wq = (const float*)d_in[4];
    const float* Wk = (const float*)d_in[5];
    const float* Wv = (const float*)d_in[6];
    const float* Wo = (const float*)d_in[7];
    float* out = (float*)d_out;

    float *Qh, *Kh, *Vh, *AO;
    float *qR, *kR, *vR, *WqR, *WkR, *WvR, *WoR;
    cudaGetSymbolAddress((void**)&Qh, g_Qh);
    cudaGetSymbolAddress((void**)&Kh, g_Kh);
    cudaGetSymbolAddress((void**)&Vh, g_Vh);
    cudaGetSymbolAddress((void**)&AO, g_AO);
    cudaGetSymbolAddress((void**)&qR, g_qR);
    cudaGetSymbolAddress((void**)&kR, g_kR);
    cudaGetSymbolAddress((void**)&vR, g_vR);
    cudaGetSymbolAddress((void**)&WqR, g_WqR);
    cudaGetSymbolAddress((void**)&WkR, g_WkR);
    cudaGetSymbolAddress((void**)&WvR, g_WvR);
    cudaGetSymbolAddress((void**)&WoR, g_WoR);

    // Prepass: round all GEMM operands to tf32 once (bandwidth-bound)
    const int n4_big = MM * DD / 4;    // 2M float4
    const int n4_w   = DD * DD / 4;    // 256K float4
    round_tf32_kernel<<<1184, 256>>>(q, qR, n4_big);
    round_tf32_kernel<<<1184, 256>>>(k, kR, n4_big);
    round_tf32_kernel<<<1184, 256>>>(v, vR, n4_big);
    round_tf32_kernel<<<592, 256>>>(Wq, WqR, n4_w);
    round_tf32_kernel<<<592, 256>>>(Wk, WkR, n4_w);
    round_tf32_kernel<<<592, 256>>>(Wv, WvR, n4_w);
    round_tf32_kernel<<<592, 256>>>(Wo, WoR, n4_w);

    dim3 ggrid(DD / 128, MM / 128);   // (8, 64)
    dim3 gblk(256);

    // Projections with fused head-split transpose (TF32 tensor cores, no cvt)
    gemm_tf32_kernel<1><<<ggrid, gblk>>>(qR, WqR, Qh);
    gemm_tf32_kernel<1><<<ggrid, gblk>>>(kR, WkR, Kh);
    gemm_tf32_kernel<1><<<ggrid, gblk>>>(vR, WvR, Vh);

    // Causal flash attention -> AO [B,L,D] (tf32-rounded output)
    dim3 fgrid(LL / 128, BB * HH);    // (16, 64)
    flash_attn_kernel<<<fgrid, 128>>>(Qh, Kh, Vh, AO);

    // Output projection -> d_out (TF32 tensor cores, no cvt)
    gemm_tf32_kernel<0><<<ggrid, gblk>>>(AO, WoR, out);
}